// round 16
// baseline (speedup 1.0000x reference)
#include <cuda_runtime.h>
#include <cuda.h>
#include <cuda_fp16.h>
#include <math.h>
#include <stdint.h>

// Problem constants
#define BB 8
#define SS 2048
#define DD 1024

// Tiles (fp16): one SW128 row = 128 bytes = 64 fp16 K-elements
#define BM 128
#define BN 256
#define BK 64

// tcgen05 only exists in the arch-specific (sm_103a) compilation pass.
#if defined(__CUDA_ARCH_FEAT_SM103_ALL) || defined(__CUDA_ARCH_FEAT_SM100_ALL) || \
    (defined(__CUDA_ARCH_SPECIFIC__) && (__CUDA_ARCH__ >= 1000))
#define HAS_TCGEN05 1
#else
#define HAS_TCGEN05 0
#endif

// Scratch (allocation-free rule: __device__ globals), all fp16 operands
__device__ __half g_XH[BB * SS * DD];         // input fp16
__device__ __half g_CH[BB * SS * DD];         // context fp16
__device__ __half g_WTH[4][DD * DD];          // WqT,WkT,WvT,WoT fp16
__device__ __half g_QH[BB * SS * DD];
__device__ __half g_KH[BB * SS * DD];
__device__ __half g_VTH[BB * SS * DD];        // V^T per batch [B, D, S] (written by V GEMM)
__device__ __half g_WH[(long long)BB * SS * SS];  // softmax weights fp16 copy
__device__ __half g_CTXH[BB * SS * DD];

// ---------------------------------------------------------------------------
// PTX helpers
// ---------------------------------------------------------------------------
__device__ __forceinline__ uint32_t smem_u32(const void* p) {
    uint32_t a;
    asm("{ .reg .u64 t; cvta.to.shared.u64 t, %1; cvt.u32.u64 %0, t; }" : "=r"(a) : "l"(p));
    return a;
}

#if HAS_TCGEN05
__device__ __forceinline__ uint32_t elect_one() {
    uint32_t pred;
    asm volatile("{\n\t.reg .pred p;\n\telect.sync _|p, 0xFFFFFFFF;\n\tselp.b32 %0, 1, 0, p;\n\t}" : "=r"(pred));
    return pred;
}
#define MBAR_INIT(addr, cnt) \
    asm volatile("mbarrier.init.shared.b64 [%0], %1;" :: "r"(addr), "r"(cnt) : "memory")
#define MBAR_WAIT(addr, par) do {                                              \
    uint32_t _m = (addr), _p = (par), _d;                                      \
    asm volatile("{\n\t.reg .pred p;\n\t"                                      \
        "mbarrier.try_wait.parity.acquire.cta.shared::cta.b64 p, [%1], %2;\n\t"\
        "selp.b32 %0, 1, 0, p;\n\t}" : "=r"(_d) : "r"(_m), "r"(_p) : "memory");\
    if (!_d) {                                                                 \
        asm volatile("{\n\t.reg .pred P1;\n\t"                                 \
        "W_%=:\n\t"                                                            \
        "mbarrier.try_wait.parity.acquire.cta.shared::cta.b64 P1, [%0], %1, 0x989680;\n\t" \
        "@P1 bra.uni D_%=;\n\tbra.uni W_%=;\n\tD_%=:\n\t}"                     \
        :: "r"(_m), "r"(_p) : "memory");                                       \
    }                                                                          \
} while (0)
#define MBAR_EXPECT_TX(addr, bytes) \
    asm volatile("mbarrier.arrive.expect_tx.shared.b64 _, [%0], %1;" \
                 :: "r"(addr), "r"(bytes) : "memory")
#define TMA_LOAD3D(smem, mapp, cx, cy, cz, mbar) \
    asm volatile("cp.async.bulk.tensor.3d.shared::cta.global.tile.mbarrier::complete_tx::bytes " \
                 "[%0], [%1, {%2, %3, %4}], [%5];" \
                 :: "r"(smem), "l"(mapp), "r"(cx), "r"(cy), "r"(cz), "r"(mbar) : "memory")
#define TMA_LOAD3D_MC(smem, mapp, cx, cy, cz, mbar, mask) \
    asm volatile("cp.async.bulk.tensor.3d.shared::cluster.global.tile.mbarrier::complete_tx::bytes.multicast::cluster " \
                 "[%0], [%1, {%2, %3, %4}], [%5], %6;" \
                 :: "r"(smem), "l"(mapp), "r"(cx), "r"(cy), "r"(cz), "r"(mbar), \
                    "h"((uint16_t)(mask)) : "memory")
#define CLUSTER_SYNC() do {                                                    \
    asm volatile("barrier.cluster.arrive.aligned;" ::: "memory");              \
    asm volatile("barrier.cluster.wait.aligned;" ::: "memory");                \
} while (0)

#define TCG_ALLOC(smem_addr, n) \
    asm volatile("tcgen05.alloc.cta_group::1.sync.aligned.shared::cta.b32 [%0], %1;" :: "r"(smem_addr), "r"(n) : "memory")
#define TCG_RELINQ() \
    asm volatile("tcgen05.relinquish_alloc_permit.cta_group::1.sync.aligned;")
#define TCG_DEALLOC(tmem, n) \
    asm volatile("tcgen05.dealloc.cta_group::1.sync.aligned.b32 %0, %1;" :: "r"(tmem), "r"(n))
// cg1 commit that arrives on the same-offset mbarrier in every masked CTA.
#define TCG_COMMIT_MC(mbar, mask) \
    asm volatile("tcgen05.commit.cta_group::1.mbarrier::arrive::one.shared::cluster.multicast::cluster.b64 [%0], %1;" \
                 :: "r"(mbar), "h"((uint16_t)(mask)) : "memory")
#define TCG_FENCE_BEFORE() asm volatile("tcgen05.fence::before_thread_sync;" ::: "memory")
#define TCG_FENCE_AFTER()  asm volatile("tcgen05.fence::after_thread_sync;" ::: "memory")
#define TCG_WAIT_LD()      asm volatile("tcgen05.wait::ld.sync.aligned;" ::: "memory")

#define TCG_LD_X32(r, tmem)                                                    \
    asm volatile("tcgen05.ld.sync.aligned.32x32b.x32.b32 "                     \
        "{%0, %1, %2, %3, %4, %5, %6, %7, %8, %9, %10, %11, %12, %13, %14, %15, " \
        " %16, %17, %18, %19, %20, %21, %22, %23, %24, %25, %26, %27, %28, %29, %30, %31}, [%32];" \
        : "=r"((r)[0]),  "=r"((r)[1]),  "=r"((r)[2]),  "=r"((r)[3]),           \
          "=r"((r)[4]),  "=r"((r)[5]),  "=r"((r)[6]),  "=r"((r)[7]),           \
          "=r"((r)[8]),  "=r"((r)[9]),  "=r"((r)[10]), "=r"((r)[11]),          \
          "=r"((r)[12]), "=r"((r)[13]), "=r"((r)[14]), "=r"((r)[15]),          \
          "=r"((r)[16]), "=r"((r)[17]), "=r"((r)[18]), "=r"((r)[19]),          \
          "=r"((r)[20]), "=r"((r)[21]), "=r"((r)[22]), "=r"((r)[23]),          \
          "=r"((r)[24]), "=r"((r)[25]), "=r"((r)[26]), "=r"((r)[27]),          \
          "=r"((r)[28]), "=r"((r)[29]), "=r"((r)[30]), "=r"((r)[31])           \
        : "r"(tmem))

// SW128 K-major SMEM descriptor (layout 2, version 1, LBO=1, SBO=64)
__device__ __forceinline__ uint64_t make_desc(uint32_t addr) {
    const uint64_t base = (uint64_t(2) << 61) | (uint64_t(1) << 46)
                        | (uint64_t(64) << 32) | (uint64_t(1) << 16);
    return base | ((uint64_t)(addr >> 4) & 0x3FFF);
}

// idesc kind::f16, fp16 inputs, fp32 accum
#define IDESC_F16 ((1u << 4) | ((BN / 8) << 17) | ((BM / 16) << 24))

__device__ __forceinline__ void mma_f16_ss(uint32_t d_tmem, uint64_t a_desc,
                                           uint64_t b_desc, uint32_t enable) {
    asm volatile(
        "{\n\t.reg .pred p;\n\t"
        "setp.ne.u32 p, %4, 0;\n\t"
        "tcgen05.mma.cta_group::1.kind::f16 [%0], %1, %2, %3, {%5, %5, %5, %5}, p;\n\t}"
        :: "r"(d_tmem), "l"(a_desc), "l"(b_desc), "r"(IDESC_F16),
           "r"(enable), "r"(0u)
        : "memory");
}
#endif // HAS_TCGEN05

// SMEM layout (dynamic): [0]=tmem ptr, mbarriers, tiles 1024-aligned
#define SM_TMEMPTR 0
#define SM_FULL0   8
#define SM_FULL1   16
#define SM_DONE0   24
#define SM_DONE1   32
#define SM_A0      1024
#define SM_A1      (SM_A0 + BM * 128)            // A tile = 16KB
#define SM_B0      (SM_A1 + BM * 128)
#define SM_B1      (SM_B0 + BN * 128)            // B tile = 32KB
#define SM_TOTAL   (SM_B1 + BN * 128)            // 99328
#define CHUNK_BYTES (BM * 128 + BN * 128)        // 49152 (A + full B)
#define BHALF_BYTES (128 * 128)                  // 16KB per multicast half

// ---------------------------------------------------------------------------
// fp16 NT GEMM on tcgen05, TMA fills, B multicast across cluster pair:
//   C[m][n] = alpha * sum_k A[m][k] * B[n][k]
// Cluster (2,1,1) along grid.x = M tiles: paired CTAs share the SAME B tile
// (same blockIdx.y). Rank r multicasts B rows [nBase + r*128, +128) to both
// CTAs; A is a per-CTA plain TMA load. MMA stays per-CTA cg1; buffer reuse
// is gated by done-barriers (count=2) armed via cg1 MULTICAST commits, so a
// stage is recycled only after BOTH CTAs' MMAs consumed it.
// tmapA: 3D (K, Mtot, batch) box (64,128,1); tmapB: box (64,128,1).
// outMode: 0 = fp32 C[M,ldc]; 1 = fp16 C[M,ldc];
//          2 = fp16 TRANSPOSED per-batch: C[b][n][s] with mGlobal=b*SS+s.
// ---------------------------------------------------------------------------
__global__ void __launch_bounds__(256) __cluster_dims__(2, 1, 1)
gemm_nt_f16(const __grid_constant__ CUtensorMap tmapA,
            const __grid_constant__ CUtensorMap tmapB,
            const __half* __restrict__ A, const __half* __restrict__ B,
            void* __restrict__ Cv, int K, int ldc,
            long long sA, long long sB, long long sC, float alpha, int outMode)
{
    const int tid = threadIdx.x;
    // grid.x = M tiles (clustered in pairs), grid.y = N tiles, grid.z = batch
    const long long cOff = (long long)blockIdx.z * sC
                         + (long long)blockIdx.x * BM * ldc
                         + (long long)blockIdx.y * BN;

#if HAS_TCGEN05
    extern __shared__ char smem[];
    const uint32_t sbase = smem_u32(smem);
    const int wid = tid >> 5;
    const int lid = tid & 31;
    const int rank = blockIdx.x & 1;

    if (wid == 0) {
        TCG_ALLOC(sbase + SM_TMEMPTR, 256);
        TCG_RELINQ();
    }
    if (tid == 0) {
        MBAR_INIT(sbase + SM_FULL0, 1);     // expect_tx arrive flips it
        MBAR_INIT(sbase + SM_FULL1, 1);
        MBAR_INIT(sbase + SM_DONE0, 2);     // both CTAs' multicast commits
        MBAR_INIT(sbase + SM_DONE1, 2);
    }
    __syncthreads();
    CLUSTER_SYNC();                         // barriers visible before multicast
    uint32_t tmem;
    asm volatile("ld.shared.b32 %0, [%1];" : "=r"(tmem) : "r"(sbase + SM_TMEMPTR));

    const int KT = K / BK;
    const int mBase = blockIdx.x * BM;
    const int nBase = blockIdx.y * BN;
    const int bIdx  = blockIdx.z;

    if (wid == 0) {
        // ---- Producer: one elected thread; A plain TMA, B-half multicast ----
        if (elect_one()) {
            for (int j = 0; j < KT; j++) {
                const int buf = j & 1;
                const int use = j >> 1;
                if (use > 0)
                    MBAR_WAIT(sbase + (buf ? SM_DONE1 : SM_DONE0), (use - 1) & 1);
                const uint32_t full = sbase + (buf ? SM_FULL1 : SM_FULL0);
                MBAR_EXPECT_TX(full, CHUNK_BYTES);
                TMA_LOAD3D(sbase + (buf ? SM_A1 : SM_A0), &tmapA,
                           j * BK, mBase, bIdx, full);
                // This CTA's half of B -> same offset in BOTH CTAs' SMEM.
                TMA_LOAD3D_MC(sbase + (buf ? SM_B1 : SM_B0) + rank * BHALF_BYTES,
                              &tmapB, j * BK, nBase + rank * 128, bIdx,
                              full, 0x3);
            }
        }
    } else if (wid == 1) {
        // ---- Consumer: one elected thread issues all MMAs (cg1, local) ----
        if (elect_one()) {
            for (int ic = 0; ic < KT; ic++) {
                const int buf = ic & 1;
                MBAR_WAIT(sbase + (buf ? SM_FULL1 : SM_FULL0), (ic >> 1) & 1);
                const uint32_t aBase = sbase + (buf ? SM_A1 : SM_A0);
                const uint32_t bBase = sbase + (buf ? SM_B1 : SM_B0);
                const uint64_t ad = make_desc(aBase);
                const uint64_t bd = make_desc(bBase);
                #pragma unroll
                for (int s = 0; s < 4; s++) {
                    mma_f16_ss(tmem, ad + s * 2, bd + s * 2,
                               (ic > 0 || s > 0) ? 1u : 0u);
                }
                // Multicast commit: arrives on done(buf) in BOTH CTAs.
                TCG_COMMIT_MC(sbase + (buf ? SM_DONE1 : SM_DONE0), 0x3);
            }
            // Final wait: done(lastBuf) flips once per use (2 arrivals, cnt=2).
            const int lastBuf = (KT - 1) & 1;
            const int cnt = (KT + 1) >> 1;
            MBAR_WAIT(sbase + (lastBuf ? SM_DONE1 : SM_DONE0), (cnt - 1) & 1);
        }
    }
    __syncthreads();                 // releases everyone once local MMAs done
    TCG_FENCE_AFTER();

    // Epilogue: 8 warps; rows (wid&3)*32+lid, col half (wid>>2)*128.
    {
        const int m = (wid & 3) * 32 + lid;
        const int chalf = (wid >> 2) * 128;
        const long long mG = (long long)blockIdx.x * BM + m;
        const long long b2 = mG >> 11;            // /SS
        const long long s2 = mG & (SS - 1);
        __half* tbase = (__half*)Cv + b2 * ((long long)DD * SS) + s2
                      + (long long)(blockIdx.y * BN + chalf) * SS;
        #pragma unroll
        for (int jp = 0; jp < 2; jp++) {          // 2 pairs of 32-col groups
            uint32_t r0[32], r1[32];
            TCG_LD_X32(r0, tmem + chalf + (jp * 2 + 0) * 32);
            TCG_LD_X32(r1, tmem + chalf + (jp * 2 + 1) * 32);
            TCG_WAIT_LD();
            float f[64];
            #pragma unroll
            for (int c = 0; c < 32; c++) f[c]      = __uint_as_float(r0[c]) * alpha;
            #pragma unroll
            for (int c = 0; c < 32; c++) f[32 + c] = __uint_as_float(r1[c]) * alpha;
            if (outMode == 0) {
                float* crow = (float*)Cv + cOff + (long long)m * ldc + chalf + jp * 64;
                #pragma unroll
                for (int c = 0; c < 16; c++)
                    *reinterpret_cast<float4*>(crow + c * 4) =
                        *reinterpret_cast<float4*>(&f[c * 4]);
            } else if (outMode == 1) {
                __half* crow = (__half*)Cv + cOff + (long long)m * ldc + chalf + jp * 64;
                #pragma unroll
                for (int c = 0; c < 8; c++) {
                    __half2 p0 = __floats2half2_rn(f[c*8+0], f[c*8+1]);
                    __half2 p1 = __floats2half2_rn(f[c*8+2], f[c*8+3]);
                    __half2 p2 = __floats2half2_rn(f[c*8+4], f[c*8+5]);
                    __half2 p3 = __floats2half2_rn(f[c*8+6], f[c*8+7]);
                    uint4 v = make_uint4(*(uint32_t*)&p0, *(uint32_t*)&p1,
                                         *(uint32_t*)&p2, *(uint32_t*)&p3);
                    *reinterpret_cast<uint4*>(crow + c * 8) = v;
                }
            } else {
                // Transposed fp16: element (m, n) -> C[b][n][s].
                #pragma unroll
                for (int c = 0; c < 64; c++)
                    tbase[(long long)(jp * 64 + c) * SS] = __float2half(f[c]);
            }
        }
    }
    TCG_FENCE_BEFORE();
    __syncthreads();
    if (wid == 0) TCG_DEALLOC(tmem, 256);
    CLUSTER_SYNC();                  // no exit while peer multicast may land

#else
    // Baseline-pass fallback (never selected at runtime on sm_103a).
    const __half* Ap = A + (long long)blockIdx.z * sA + (long long)blockIdx.x * BM * K;
    const __half* Bp = B + (long long)blockIdx.z * sB + (long long)blockIdx.y * BN * K;
    const int trow = (tid >> 4) * 8;
    const int tcol = (tid & 15) * 16;
    float acc[8][16];
    #pragma unroll
    for (int i = 0; i < 8; i++)
        #pragma unroll
        for (int j = 0; j < 16; j++) acc[i][j] = 0.f;
    for (int k = 0; k < K; k++) {
        float ar[8], br[16];
        #pragma unroll
        for (int i = 0; i < 8; i++) ar[i] = __half2float(Ap[(long long)(trow + i) * K + k]);
        #pragma unroll
        for (int j = 0; j < 16; j++) br[j] = __half2float(Bp[(long long)(tcol + j) * K + k]);
        #pragma unroll
        for (int i = 0; i < 8; i++)
            #pragma unroll
            for (int j = 0; j < 16; j++)
                acc[i][j] = fmaf(ar[i], br[j], acc[i][j]);
    }
    #pragma unroll
    for (int i = 0; i < 8; i++)
        #pragma unroll
        for (int j = 0; j < 16; j++) {
            const float val = acc[i][j] * alpha;
            if (outMode == 2) {
                const long long mG = (long long)blockIdx.x * BM + trow + i;
                const long long b2 = mG >> 11, s2 = mG & (SS - 1);
                const long long n = blockIdx.y * BN + tcol + j;
                ((__half*)Cv)[b2 * ((long long)DD * SS) + n * SS + s2] = __float2half(val);
            } else {
                const long long idx = cOff + (long long)(trow + i) * ldc + tcol + j;
                if (outMode == 1) ((__half*)Cv)[idx] = __float2half(val);
                else              ((float*)Cv)[idx] = val;
            }
        }
#endif
}

// ---------------------------------------------------------------------------
// Fused dual convert fp32 -> fp16 (input + context in one launch)
// ---------------------------------------------------------------------------
__global__ void __launch_bounds__(256)
cvt2_f32_f16(const float* __restrict__ in0, __half* __restrict__ out0,
             const float* __restrict__ in1, __half* __restrict__ out1,
             long long n)
{
    const long long i = ((long long)blockIdx.x * 256 + threadIdx.x) * 4;
    if (i + 3 < n) {
        float4 v = *reinterpret_cast<const float4*>(in0 + i);
        __half2 a = __floats2half2_rn(v.x, v.y);
        __half2 b = __floats2half2_rn(v.z, v.w);
        *reinterpret_cast<uint2*>(out0 + i) =
            make_uint2(*(uint32_t*)&a, *(uint32_t*)&b);
        float4 w = *reinterpret_cast<const float4*>(in1 + i);
        __half2 c = __floats2half2_rn(w.x, w.y);
        __half2 d = __floats2half2_rn(w.z, w.w);
        *reinterpret_cast<uint2*>(out1 + i) =
            make_uint2(*(uint32_t*)&c, *(uint32_t*)&d);
    }
}

// ---------------------------------------------------------------------------
// Batched transpose fp32 -> fp16: out[z][c][r] = (half) in[z][r][c]
// ---------------------------------------------------------------------------
__global__ void __launch_bounds__(256)
transpose4_f32_to_f16(const float* __restrict__ w0, const float* __restrict__ w1,
                      const float* __restrict__ w2, const float* __restrict__ w3,
                      __half* __restrict__ outBase)
{
    __shared__ float t[32][33];
    const float* in = (blockIdx.z == 0) ? w0 : (blockIdx.z == 1) ? w1
                    : (blockIdx.z == 2) ? w2 : w3;
    __half* out = outBase + (long long)blockIdx.z * DD * DD;
    const int c0 = blockIdx.x * 32, r0 = blockIdx.y * 32;
    #pragma unroll
    for (int i = threadIdx.y; i < 32; i += 8)
        t[i][threadIdx.x] = in[(long long)(r0 + i) * DD + c0 + threadIdx.x];
    __syncthreads();
    #pragma unroll
    for (int i = threadIdx.y; i < 32; i += 8)
        out[(long long)(c0 + i) * DD + r0 + threadIdx.x] = __float2half(t[threadIdx.x][i]);
}

// ---------------------------------------------------------------------------
// Row softmax in place (fp32) + fp16 copy. One block per row, 256 threads.
// ---------------------------------------------------------------------------
__inline__ __device__ float warpMax(float v) {
    #pragma unroll
    for (int o = 16; o > 0; o >>= 1) v = fmaxf(v, __shfl_xor_sync(0xffffffffu, v, o));
    return v;
}
__inline__ __device__ float warpSum(float v) {
    #pragma unroll
    for (int o = 16; o > 0; o >>= 1) v += __shfl_xor_sync(0xffffffffu, v, o);
    return v;
}

__global__ void __launch_bounds__(256)
softmax_rows(float* __restrict__ W, __half* __restrict__ WH)
{
    float* row = W + (long long)blockIdx.x * SS;
    __half* hrow = WH + (long long)blockIdx.x * SS;
    const int tid = threadIdx.x;
    const int base = tid * 8;
    __shared__ float red[8];

    float4 v0 = *reinterpret_cast<const float4*>(row + base);
    float4 v1 = *reinterpret_cast<const float4*>(row + base + 4);
    float v[8] = { v0.x, v0.y, v0.z, v0.w, v1.x, v1.y, v1.z, v1.w };

    float m = v[0];
    #pragma unroll
    for (int i = 1; i < 8; i++) m = fmaxf(m, v[i]);
    m = warpMax(m);
    if ((tid & 31) == 0) red[tid >> 5] = m;
    __syncthreads();
    if (tid < 32) {
        float t = (tid < 8) ? red[tid] : -INFINITY;
        t = warpMax(t);
        if (tid == 0) red[0] = t;
    }
    __syncthreads();
    m = red[0];

    float s = 0.f;
    #pragma unroll
    for (int i = 0; i < 8; i++) {
        v[i] = __expf(v[i] - m);
        s += v[i];
    }
    s = warpSum(s);
    __syncthreads();
    if ((tid & 31) == 0) red[tid >> 5] = s;
    __syncthreads();
    if (tid < 32) {
        float t = (tid < 8) ? red[tid] : 0.f;
        t = warpSum(t);
        if (tid == 0) red[0] = t;
    }
    __syncthreads();
    const float inv = 1.0f / red[0];

    #pragma unroll
    for (int i = 0; i < 8; i++) v[i] *= inv;

    *reinterpret_cast<float4*>(row + base)     = make_float4(v[0], v[1], v[2], v[3]);
    *reinterpret_cast<float4*>(row + base + 4) = make_float4(v[4], v[5], v[6], v[7]);
    __half2 h0 = __floats2half2_rn(v[0], v[1]);
    __half2 h1 = __floats2half2_rn(v[2], v[3]);
    __half2 h2 = __floats2half2_rn(v[4], v[5]);
    __half2 h3 = __floats2half2_rn(v[6], v[7]);
    uint4 hv = make_uint4(*(uint32_t*)&h0, *(uint32_t*)&h1,
                          *(uint32_t*)&h2, *(uint32_t*)&h3);
    *reinterpret_cast<uint4*>(hrow + base) = hv;
}

// ---------------------------------------------------------------------------
// Host-side tensormap construction (driver entry point via cudart; no -lcuda)
// ---------------------------------------------------------------------------
typedef CUresult (*PFN_tmapEncode)(
    CUtensorMap*, CUtensorMapDataType, cuuint32_t, void*,
    const cuuint64_t*, const cuuint64_t*, const cuuint32_t*, const cuuint32_t*,
    CUtensorMapInterleave, CUtensorMapSwizzle, CUtensorMapL2promotion,
    CUtensorMapFloatOOBfill);

static PFN_tmapEncode get_tmap_encode() {
    void* fn = nullptr;
    cudaDriverEntryPointQueryResult st;
#if CUDART_VERSION >= 12050
    cudaGetDriverEntryPointByVersion("cuTensorMapEncodeTiled", &fn, 12000,
                                     cudaEnableDefault, &st);
#else
    cudaGetDriverEntryPoint("cuTensorMapEncodeTiled", &fn, cudaEnableDefault, &st);
#endif
    return (PFN_tmapEncode)fn;
}

static void make_tmap(PFN_tmapEncode enc, CUtensorMap* out, void* base,
                      long long K, long long rows, long long batch,
                      long long rowPitchBytes, long long batchStrideBytes,
                      uint32_t boxK, uint32_t boxRows)
{
    cuuint64_t dims[3]    = { (cuuint64_t)K, (cuuint64_t)rows, (cuuint64_t)batch };
    cuuint64_t strides[2] = { (cuuint64_t)rowPitchBytes, (cuuint64_t)batchStrideBytes };
    cuuint32_t box[3]     = { boxK, boxRows, 1 };
    cuuint32_t es[3]      = { 1, 1, 1 };
    enc(out, CU_TENSOR_MAP_DATA_TYPE_UINT16, 3, base, dims, strides, box, es,
        CU_TENSOR_MAP_INTERLEAVE_NONE, CU_TENSOR_MAP_SWIZZLE_128B,
        CU_TENSOR_MAP_L2_PROMOTION_L2_128B, CU_TENSOR_MAP_FLOAT_OOB_FILL_NONE);
}

// ---------------------------------------------------------------------------
// kernel_launch
// d_in: 0=input [B,S,D], 1=context [B,S,D], 2=Wq, 3=Wk, 4=Wv, 5=Wo ([D,D])
// d_out: output [B,S,D] then weights [B,S,S], fp32.
// ---------------------------------------------------------------------------
extern "C" void kernel_launch(void* const* d_in, const int* in_sizes, int n_in,
                              void* d_out, int out_size)
{
    const float* input   = (const float*)d_in[0];
    const float* context = (const float*)d_in[1];
    const float* Wq      = (const float*)d_in[2];
    const float* Wk      = (const float*)d_in[3];
    const float* Wv      = (const float*)d_in[4];
    const float* Wo      = (const float*)d_in[5];

    float* out     = (float*)d_out;                          // [B,S,D]
    float* weights = out + (long long)BB * SS * DD;          // [B,S,S]

    __half *xh, *ch, *wth, *qh, *kh, *vth, *wh, *ctxh;
    cudaGetSymbolAddress((void**)&xh,   g_XH);
    cudaGetSymbolAddress((void**)&ch,   g_CH);
    cudaGetSymbolAddress((void**)&wth,  g_WTH);
    cudaGetSymbolAddress((void**)&qh,   g_QH);
    cudaGetSymbolAddress((void**)&kh,   g_KH);
    cudaGetSymbolAddress((void**)&vth,  g_VTH);
    cudaGetSymbolAddress((void**)&wh,   g_WH);
    cudaGetSymbolAddress((void**)&ctxh, g_CTXH);
    __half* WqT = wth;
    __half* WkT = wth + 1 * DD * DD;
    __half* WvT = wth + 2 * DD * DD;
    __half* WoT = wth + 3 * DD * DD;

    cudaFuncSetAttribute(gemm_nt_f16,
                         cudaFuncAttributeMaxDynamicSharedMemorySize, SM_TOTAL);

    const dim3 blk(256);
    const dim3 tblk(32, 8);
    const long long SD  = (long long)SS * DD;
    const long long SSq = (long long)SS * SS;
    const long long NX  = (long long)BB * SS * DD;

    // Tensormaps. B maps use box rows = 128 (one multicast half per load).
    PFN_tmapEncode enc = get_tmap_encode();
    CUtensorMap tA_x, tA_c, tB_wq, tB_wk, tB_wv, tB_wo;
    CUtensorMap tA_q, tB_k, tA_w, tB_vt, tA_ctx;
    make_tmap(enc, &tA_x,   xh,  DD, (long long)BB * SS, 1, DD * 2, NX * 2, BK, BM);
    make_tmap(enc, &tA_c,   ch,  DD, (long long)BB * SS, 1, DD * 2, NX * 2, BK, BM);
    make_tmap(enc, &tB_wq,  WqT, DD, DD, 1, DD * 2, (long long)DD * DD * 2, BK, 128);
    make_tmap(enc, &tB_wk,  WkT, DD, DD, 1, DD * 2, (long long)DD * DD * 2, BK, 128);
    make_tmap(enc, &tB_wv,  WvT, DD, DD, 1, DD * 2, (long long)DD * DD * 2, BK, 128);
    make_tmap(enc, &tB_wo,  WoT, DD, DD, 1, DD * 2, (long long)DD * DD * 2, BK, 128);
    make_tmap(enc, &tA_q,   qh,  DD, SS, BB, DD * 2, SD * 2, BK, BM);
    make_tmap(enc, &tB_k,   kh,  DD, SS, BB, DD * 2, SD * 2, BK, 128);
    make_tmap(enc, &tA_w,   wh,  SS, SS, BB, SS * 2, SSq * 2, BK, BM);
    make_tmap(enc, &tB_vt,  vth, SS, DD, BB, SS * 2, SD * 2, BK, 128);
    make_tmap(enc, &tA_ctx, ctxh, DD, (long long)BB * SS, 1, DD * 2, NX * 2, BK, BM);

    // 0) Fused prologue: dual cvt (1 launch) + batched weight transpose (1 launch)
    cvt2_f32_f16<<<(unsigned)((NX / 4 + 255) / 256), blk>>>(input, xh, context, ch, NX);
    {
        dim3 g(DD / 32, DD / 32, 4);
        transpose4_f32_to_f16<<<g, tblk>>>(Wq, Wk, Wv, Wo, wth);
    }

    // Grid: x = M tiles (even, clustered), y = N tiles, z = batch
    // 1) Projections: Q,K fp16; V written TRANSPOSED directly (mode 2)
    {
        dim3 g((BB * SS) / BM, DD / BN, 1);
        gemm_nt_f16<<<g, blk, SM_TOTAL>>>(tA_x, tB_wq, xh, WqT, qh,  DD, DD, 0, 0, 0, 1.0f, 1);
        gemm_nt_f16<<<g, blk, SM_TOTAL>>>(tA_c, tB_wk, ch, WkT, kh,  DD, DD, 0, 0, 0, 1.0f, 1);
        gemm_nt_f16<<<g, blk, SM_TOTAL>>>(tA_c, tB_wv, ch, WvT, vth, DD, DD, 0, 0, 0, 1.0f, 2);
    }

    // 2) scores = Q @ K^T * (1/sqrt(D)) -> weights slice (fp32 out)
    {
        dim3 g(SS / BM, SS / BN, BB);
        gemm_nt_f16<<<g, blk, SM_TOTAL>>>(tA_q, tB_k, qh, kh, weights, DD, SS, SD, SD, SSq, 0.03125f, 0);
    }

    // 3) softmax in place (fp32) + fp16 copy
    softmax_rows<<<BB * SS, blk>>>(weights, wh);

    // 4) ctx = weights @ V == NT with V^T rows (fp16 out)
    {
        dim3 g(SS / BM, DD / BN, BB);
        gemm_nt_f16<<<g, blk, SM_TOTAL>>>(tA_w, tB_vt, wh, vth, ctxh, SS, DD, SSq, SD, SD, 1.0f, 1);
    }

    // 5) output = ctx @ Wo == NT with Wo^T (fp32 out)
    {
        dim3 g((BB * SS) / BM, DD / BN, 1);
        gemm_nt_f16<<<g, blk, SM_TOTAL>>>(tA_ctx, tB_wo, ctxh, WoT, out, DD, DD, 0, 0, 0, 1.0f, 0);
    }
}

// round 17
// speedup vs baseline: 1.1223x; 1.1223x over previous
#include <cuda_runtime.h>
#include <cuda.h>
#include <cuda_fp16.h>
#include <math.h>
#include <stdint.h>

// Problem constants
#define BB 8
#define SS 2048
#define DD 1024

// Tiles (fp16): 256x256 per CTA (two M=128 atoms), BK=64 (=128B SW128 row)
#define BM 256
#define BN 256
#define BK 64
#define NSTAGE 3

// tcgen05 only exists in the arch-specific (sm_103a) compilation pass.
#if defined(__CUDA_ARCH_FEAT_SM103_ALL) || defined(__CUDA_ARCH_FEAT_SM100_ALL) || \
    (defined(__CUDA_ARCH_SPECIFIC__) && (__CUDA_ARCH__ >= 1000))
#define HAS_TCGEN05 1
#else
#define HAS_TCGEN05 0
#endif

// Scratch (allocation-free rule: __device__ globals), all fp16 operands
__device__ __half g_XH[BB * SS * DD];         // input fp16
__device__ __half g_CH[BB * SS * DD];         // context fp16
__device__ __half g_WTH[4][DD * DD];          // WqT,WkT,WvT,WoT fp16
__device__ __half g_QH[BB * SS * DD];
__device__ __half g_KH[BB * SS * DD];
__device__ __half g_VTH[BB * SS * DD];        // V^T per batch [B, D, S] (written by V GEMM)
__device__ __half g_WH[(long long)BB * SS * SS];  // softmax weights fp16 copy
__device__ __half g_CTXH[BB * SS * DD];

// ---------------------------------------------------------------------------
// PTX helpers
// ---------------------------------------------------------------------------
__device__ __forceinline__ uint32_t smem_u32(const void* p) {
    uint32_t a;
    asm("{ .reg .u64 t; cvta.to.shared.u64 t, %1; cvt.u32.u64 %0, t; }" : "=r"(a) : "l"(p));
    return a;
}

#if HAS_TCGEN05
__device__ __forceinline__ uint32_t elect_one() {
    uint32_t pred;
    asm volatile("{\n\t.reg .pred p;\n\telect.sync _|p, 0xFFFFFFFF;\n\tselp.b32 %0, 1, 0, p;\n\t}" : "=r"(pred));
    return pred;
}
#define MBAR_INIT(addr, cnt) \
    asm volatile("mbarrier.init.shared.b64 [%0], %1;" :: "r"(addr), "r"(cnt) : "memory")
#define MBAR_WAIT(addr, par) do {                                              \
    uint32_t _m = (addr), _p = (par), _d;                                      \
    asm volatile("{\n\t.reg .pred p;\n\t"                                      \
        "mbarrier.try_wait.parity.acquire.cta.shared::cta.b64 p, [%1], %2;\n\t"\
        "selp.b32 %0, 1, 0, p;\n\t}" : "=r"(_d) : "r"(_m), "r"(_p) : "memory");\
    if (!_d) {                                                                 \
        asm volatile("{\n\t.reg .pred P1;\n\t"                                 \
        "W_%=:\n\t"                                                            \
        "mbarrier.try_wait.parity.acquire.cta.shared::cta.b64 P1, [%0], %1, 0x989680;\n\t" \
        "@P1 bra.uni D_%=;\n\tbra.uni W_%=;\n\tD_%=:\n\t}"                     \
        :: "r"(_m), "r"(_p) : "memory");                                       \
    }                                                                          \
} while (0)
#define MBAR_EXPECT_TX(addr, bytes) \
    asm volatile("mbarrier.arrive.expect_tx.shared.b64 _, [%0], %1;" \
                 :: "r"(addr), "r"(bytes) : "memory")
#define TMA_LOAD3D(smem, mapp, cx, cy, cz, mbar) \
    asm volatile("cp.async.bulk.tensor.3d.shared::cta.global.tile.mbarrier::complete_tx::bytes " \
                 "[%0], [%1, {%2, %3, %4}], [%5];" \
                 :: "r"(smem), "l"(mapp), "r"(cx), "r"(cy), "r"(cz), "r"(mbar) : "memory")

#define TCG_ALLOC(smem_addr, n) \
    asm volatile("tcgen05.alloc.cta_group::1.sync.aligned.shared::cta.b32 [%0], %1;" :: "r"(smem_addr), "r"(n) : "memory")
#define TCG_RELINQ() \
    asm volatile("tcgen05.relinquish_alloc_permit.cta_group::1.sync.aligned;")
#define TCG_DEALLOC(tmem, n) \
    asm volatile("tcgen05.dealloc.cta_group::1.sync.aligned.b32 %0, %1;" :: "r"(tmem), "r"(n))
#define TCG_COMMIT(mbar) \
    asm volatile("tcgen05.commit.cta_group::1.mbarrier::arrive::one.shared::cluster.b64 [%0];" :: "r"(mbar) : "memory")
#define TCG_FENCE_BEFORE() asm volatile("tcgen05.fence::before_thread_sync;" ::: "memory")
#define TCG_FENCE_AFTER()  asm volatile("tcgen05.fence::after_thread_sync;" ::: "memory")
#define TCG_WAIT_LD()      asm volatile("tcgen05.wait::ld.sync.aligned;" ::: "memory")

#define TCG_LD_X32(r, tmem)                                                    \
    asm volatile("tcgen05.ld.sync.aligned.32x32b.x32.b32 "                     \
        "{%0, %1, %2, %3, %4, %5, %6, %7, %8, %9, %10, %11, %12, %13, %14, %15, " \
        " %16, %17, %18, %19, %20, %21, %22, %23, %24, %25, %26, %27, %28, %29, %30, %31}, [%32];" \
        : "=r"((r)[0]),  "=r"((r)[1]),  "=r"((r)[2]),  "=r"((r)[3]),           \
          "=r"((r)[4]),  "=r"((r)[5]),  "=r"((r)[6]),  "=r"((r)[7]),           \
          "=r"((r)[8]),  "=r"((r)[9]),  "=r"((r)[10]), "=r"((r)[11]),          \
          "=r"((r)[12]), "=r"((r)[13]), "=r"((r)[14]), "=r"((r)[15]),          \
          "=r"((r)[16]), "=r"((r)[17]), "=r"((r)[18]), "=r"((r)[19]),          \
          "=r"((r)[20]), "=r"((r)[21]), "=r"((r)[22]), "=r"((r)[23]),          \
          "=r"((r)[24]), "=r"((r)[25]), "=r"((r)[26]), "=r"((r)[27]),          \
          "=r"((r)[28]), "=r"((r)[29]), "=r"((r)[30]), "=r"((r)[31])           \
        : "r"(tmem))

// SW128 K-major SMEM descriptor (layout 2, version 1, LBO=1, SBO=64)
__device__ __forceinline__ uint64_t make_desc(uint32_t addr) {
    const uint64_t base = (uint64_t(2) << 61) | (uint64_t(1) << 46)
                        | (uint64_t(64) << 32) | (uint64_t(1) << 16);
    return base | ((uint64_t)(addr >> 4) & 0x3FFF);
}

// idesc kind::f16, fp16 inputs, fp32 accum; M=128 per atom, N=256
#define IDESC_F16 ((1u << 4) | ((BN / 8) << 17) | ((128 / 16) << 24))

__device__ __forceinline__ void mma_f16_ss(uint32_t d_tmem, uint64_t a_desc,
                                           uint64_t b_desc, uint32_t enable) {
    asm volatile(
        "{\n\t.reg .pred p;\n\t"
        "setp.ne.u32 p, %4, 0;\n\t"
        "tcgen05.mma.cta_group::1.kind::f16 [%0], %1, %2, %3, {%5, %5, %5, %5}, p;\n\t}"
        :: "r"(d_tmem), "l"(a_desc), "l"(b_desc), "r"(IDESC_F16),
           "r"(enable), "r"(0u)
        : "memory");
}
#endif // HAS_TCGEN05

// SMEM layout (dynamic): [0]=tmem ptr, mbarriers, 3 stages of (A 32KB + B 32KB)
#define SM_TMEMPTR 0
#define SM_FULLB   8                             // full[s] = 8 + s*8
#define SM_DONEB   32                            // done[s] = 32 + s*8
#define SM_STAGE0  1024
#define STAGE_BYTES (BM * 128 + BN * 128)        // 65536
#define SM_A(s)    (SM_STAGE0 + (s) * STAGE_BYTES)
#define SM_B(s)    (SM_A(s) + BM * 128)
#define SM_TOTAL   (SM_STAGE0 + NSTAGE * STAGE_BYTES)   // 197632
#define CHUNK_BYTES STAGE_BYTES

// ---------------------------------------------------------------------------
// fp16 NT GEMM on tcgen05 with TMA fills, 256x256 tile, 3-stage pipeline:
//   C[m][n] = alpha * sum_k A[m][k] * B[n][k]
// Two M=128 MMA atoms per K-step into TMEM halves (cols 0 / 256).
// tmapA: 3D (K, Mtot, batch) box (64,256,1); tmapB same with Ntot rows.
// outMode: 0 = fp32 C[M,ldc]; 1 = fp16 C[M,ldc];
//          2 = fp16 TRANSPOSED per-batch: C[b][n][s] with mGlobal=b*SS+s.
// Warp 0 elected = TMA producer; warp 1 elected = MMA consumer.
// ---------------------------------------------------------------------------
__global__ void __launch_bounds__(256)
gemm_nt_f16(const __grid_constant__ CUtensorMap tmapA,
            const __grid_constant__ CUtensorMap tmapB,
            const __half* __restrict__ A, const __half* __restrict__ B,
            void* __restrict__ Cv, int K, int ldc,
            long long sA, long long sB, long long sC, float alpha, int outMode)
{
    const int tid = threadIdx.x;
    const long long cOff = (long long)blockIdx.z * sC
                         + (long long)blockIdx.y * BM * ldc
                         + (long long)blockIdx.x * BN;

#if HAS_TCGEN05
    extern __shared__ char smem[];
    const uint32_t sbase = smem_u32(smem);
    const int wid = tid >> 5;
    const int lid = tid & 31;

    if (wid == 0) {
        TCG_ALLOC(sbase + SM_TMEMPTR, 512);
        TCG_RELINQ();
    }
    if (tid == 0) {
        #pragma unroll
        for (int s = 0; s < NSTAGE; s++) {
            MBAR_INIT(sbase + SM_FULLB + s * 8, 1);
            MBAR_INIT(sbase + SM_DONEB + s * 8, 1);
        }
    }
    __syncthreads();
    uint32_t tmem;
    asm volatile("ld.shared.b32 %0, [%1];" : "=r"(tmem) : "r"(sbase + SM_TMEMPTR));

    const int KT = K / BK;
    const int mBase = blockIdx.y * BM;
    const int nBase = blockIdx.x * BN;
    const int bIdx  = blockIdx.z;

    if (wid == 0) {
        // ---- Producer: one elected thread issues TMA chunk fills ----
        if (elect_one()) {
            for (int j = 0; j < KT; j++) {
                const int s = j % NSTAGE;
                const int use = j / NSTAGE;
                if (use > 0)
                    MBAR_WAIT(sbase + SM_DONEB + s * 8, (use - 1) & 1);
                const uint32_t full = sbase + SM_FULLB + s * 8;
                MBAR_EXPECT_TX(full, CHUNK_BYTES);
                TMA_LOAD3D(sbase + SM_A(s), &tmapA, j * BK, mBase, bIdx, full);
                TMA_LOAD3D(sbase + SM_B(s), &tmapB, j * BK, nBase, bIdx, full);
            }
        }
    } else if (wid == 1) {
        // ---- Consumer: one elected thread issues all MMAs ----
        if (elect_one()) {
            for (int ic = 0; ic < KT; ic++) {
                const int s = ic % NSTAGE;
                MBAR_WAIT(sbase + SM_FULLB + s * 8, (ic / NSTAGE) & 1);
                const uint64_t ad0 = make_desc(sbase + SM_A(s));
                const uint64_t ad1 = make_desc(sbase + SM_A(s) + 128 * 128);
                const uint64_t bd  = make_desc(sbase + SM_B(s));
                #pragma unroll
                for (int st = 0; st < 4; st++) {
                    const uint32_t en = (ic > 0 || st > 0) ? 1u : 0u;
                    mma_f16_ss(tmem,       ad0 + st * 2, bd + st * 2, en);
                    mma_f16_ss(tmem + 256, ad1 + st * 2, bd + st * 2, en);
                }
                TCG_COMMIT(sbase + SM_DONEB + s * 8);
            }
            // Final wait: all MMAs done (in-order per CTA).
            const int lastS = (KT - 1) % NSTAGE;
            const int cnt = (KT - 1) / NSTAGE + 1;
            MBAR_WAIT(sbase + SM_DONEB + lastS * 8, (cnt - 1) & 1);
        }
    }
    __syncthreads();                 // releases everyone once MMAs are done
    TCG_FENCE_AFTER();

    // Epilogue: warp w drains TMEM half (w>>2), rows (w&3)*32+lid, 256 cols.
    {
        const int half = wid >> 2;
        const int m = half * 128 + (wid & 3) * 32 + lid;
        const uint32_t tcolBase = tmem + half * 256;
        const long long mG = (long long)blockIdx.y * BM + m;
        const long long b2 = mG >> 11;            // /SS
        const long long s2 = mG & (SS - 1);
        __half* tbase = (__half*)Cv + b2 * ((long long)DD * SS) + s2
                      + (long long)(blockIdx.x * BN) * SS;
        #pragma unroll
        for (int jp = 0; jp < 4; jp++) {          // 4 pairs of 32-col groups
            uint32_t r0[32], r1[32];
            TCG_LD_X32(r0, tcolBase + (jp * 2 + 0) * 32);
            TCG_LD_X32(r1, tcolBase + (jp * 2 + 1) * 32);
            TCG_WAIT_LD();
            float f[64];
            #pragma unroll
            for (int c = 0; c < 32; c++) f[c]      = __uint_as_float(r0[c]) * alpha;
            #pragma unroll
            for (int c = 0; c < 32; c++) f[32 + c] = __uint_as_float(r1[c]) * alpha;
            if (outMode == 0) {
                float* crow = (float*)Cv + cOff + (long long)m * ldc + jp * 64;
                #pragma unroll
                for (int c = 0; c < 16; c++)
                    *reinterpret_cast<float4*>(crow + c * 4) =
                        *reinterpret_cast<float4*>(&f[c * 4]);
            } else if (outMode == 1) {
                __half* crow = (__half*)Cv + cOff + (long long)m * ldc + jp * 64;
                #pragma unroll
                for (int c = 0; c < 8; c++) {
                    __half2 p0 = __floats2half2_rn(f[c*8+0], f[c*8+1]);
                    __half2 p1 = __floats2half2_rn(f[c*8+2], f[c*8+3]);
                    __half2 p2 = __floats2half2_rn(f[c*8+4], f[c*8+5]);
                    __half2 p3 = __floats2half2_rn(f[c*8+6], f[c*8+7]);
                    uint4 v = make_uint4(*(uint32_t*)&p0, *(uint32_t*)&p1,
                                         *(uint32_t*)&p2, *(uint32_t*)&p3);
                    *reinterpret_cast<uint4*>(crow + c * 8) = v;
                }
            } else {
                // Transposed fp16: element (m, n) -> C[b][n][s].
                #pragma unroll
                for (int c = 0; c < 64; c++)
                    tbase[(long long)(jp * 64 + c) * SS] = __float2half(f[c]);
            }
        }
    }
    TCG_FENCE_BEFORE();
    __syncthreads();
    if (wid == 0) TCG_DEALLOC(tmem, 512);

#else
    // Baseline-pass fallback (never selected at runtime on sm_103a).
    const __half* Ap = A + (long long)blockIdx.z * sA + (long long)blockIdx.y * BM * K;
    const __half* Bp = B + (long long)blockIdx.z * sB + (long long)blockIdx.x * BN * K;
    for (int half = 0; half < 2; half++) {
        const int trow = half * 128 + (tid >> 4) * 8;
        const int tcol = (tid & 15) * 16;
        float acc[8][16];
        #pragma unroll
        for (int i = 0; i < 8; i++)
            #pragma unroll
            for (int j = 0; j < 16; j++) acc[i][j] = 0.f;
        for (int k = 0; k < K; k++) {
            float ar[8], br[16];
            #pragma unroll
            for (int i = 0; i < 8; i++) ar[i] = __half2float(Ap[(long long)(trow + i) * K + k]);
            #pragma unroll
            for (int j = 0; j < 16; j++) br[j] = __half2float(Bp[(long long)(tcol + j) * K + k]);
            #pragma unroll
            for (int i = 0; i < 8; i++)
                #pragma unroll
                for (int j = 0; j < 16; j++)
                    acc[i][j] = fmaf(ar[i], br[j], acc[i][j]);
        }
        #pragma unroll
        for (int i = 0; i < 8; i++)
            #pragma unroll
            for (int j = 0; j < 16; j++) {
                const float val = acc[i][j] * alpha;
                if (outMode == 2) {
                    const long long mG = (long long)blockIdx.y * BM + trow + i;
                    const long long b2 = mG >> 11, s2 = mG & (SS - 1);
                    const long long n = blockIdx.x * BN + tcol + j;
                    ((__half*)Cv)[b2 * ((long long)DD * SS) + n * SS + s2] = __float2half(val);
                } else {
                    const long long idx = cOff + (long long)(trow + i) * ldc + tcol + j;
                    if (outMode == 1) ((__half*)Cv)[idx] = __float2half(val);
                    else              ((float*)Cv)[idx] = val;
                }
            }
    }
#endif
}

// ---------------------------------------------------------------------------
// Fused dual convert fp32 -> fp16 (input + context in one launch)
// ---------------------------------------------------------------------------
__global__ void __launch_bounds__(256)
cvt2_f32_f16(const float* __restrict__ in0, __half* __restrict__ out0,
             const float* __restrict__ in1, __half* __restrict__ out1,
             long long n)
{
    const long long i = ((long long)blockIdx.x * 256 + threadIdx.x) * 4;
    if (i + 3 < n) {
        float4 v = *reinterpret_cast<const float4*>(in0 + i);
        __half2 a = __floats2half2_rn(v.x, v.y);
        __half2 b = __floats2half2_rn(v.z, v.w);
        *reinterpret_cast<uint2*>(out0 + i) =
            make_uint2(*(uint32_t*)&a, *(uint32_t*)&b);
        float4 w = *reinterpret_cast<const float4*>(in1 + i);
        __half2 c = __floats2half2_rn(w.x, w.y);
        __half2 d = __floats2half2_rn(w.z, w.w);
        *reinterpret_cast<uint2*>(out1 + i) =
            make_uint2(*(uint32_t*)&c, *(uint32_t*)&d);
    }
}

// ---------------------------------------------------------------------------
// Batched transpose fp32 -> fp16: out[z][c][r] = (half) in[z][r][c]
// ---------------------------------------------------------------------------
__global__ void __launch_bounds__(256)
transpose4_f32_to_f16(const float* __restrict__ w0, const float* __restrict__ w1,
                      const float* __restrict__ w2, const float* __restrict__ w3,
                      __half* __restrict__ outBase)
{
    __shared__ float t[32][33];
    const float* in = (blockIdx.z == 0) ? w0 : (blockIdx.z == 1) ? w1
                    : (blockIdx.z == 2) ? w2 : w3;
    __half* out = outBase + (long long)blockIdx.z * DD * DD;
    const int c0 = blockIdx.x * 32, r0 = blockIdx.y * 32;
    #pragma unroll
    for (int i = threadIdx.y; i < 32; i += 8)
        t[i][threadIdx.x] = in[(long long)(r0 + i) * DD + c0 + threadIdx.x];
    __syncthreads();
    #pragma unroll
    for (int i = threadIdx.y; i < 32; i += 8)
        out[(long long)(c0 + i) * DD + r0 + threadIdx.x] = __float2half(t[threadIdx.x][i]);
}

// ---------------------------------------------------------------------------
// Row softmax in place (fp32) + fp16 copy. One block per row, 256 threads.
// ---------------------------------------------------------------------------
__inline__ __device__ float warpMax(float v) {
    #pragma unroll
    for (int o = 16; o > 0; o >>= 1) v = fmaxf(v, __shfl_xor_sync(0xffffffffu, v, o));
    return v;
}
__inline__ __device__ float warpSum(float v) {
    #pragma unroll
    for (int o = 16; o > 0; o >>= 1) v += __shfl_xor_sync(0xffffffffu, v, o);
    return v;
}

__global__ void __launch_bounds__(256)
softmax_rows(float* __restrict__ W, __half* __restrict__ WH)
{
    float* row = W + (long long)blockIdx.x * SS;
    __half* hrow = WH + (long long)blockIdx.x * SS;
    const int tid = threadIdx.x;
    const int base = tid * 8;
    __shared__ float red[8];

    float4 v0 = *reinterpret_cast<const float4*>(row + base);
    float4 v1 = *reinterpret_cast<const float4*>(row + base + 4);
    float v[8] = { v0.x, v0.y, v0.z, v0.w, v1.x, v1.y, v1.z, v1.w };

    float m = v[0];
    #pragma unroll
    for (int i = 1; i < 8; i++) m = fmaxf(m, v[i]);
    m = warpMax(m);
    if ((tid & 31) == 0) red[tid >> 5] = m;
    __syncthreads();
    if (tid < 32) {
        float t = (tid < 8) ? red[tid] : -INFINITY;
        t = warpMax(t);
        if (tid == 0) red[0] = t;
    }
    __syncthreads();
    m = red[0];

    float s = 0.f;
    #pragma unroll
    for (int i = 0; i < 8; i++) {
        v[i] = __expf(v[i] - m);
        s += v[i];
    }
    s = warpSum(s);
    __syncthreads();
    if ((tid & 31) == 0) red[tid >> 5] = s;
    __syncthreads();
    if (tid < 32) {
        float t = (tid < 8) ? red[tid] : 0.f;
        t = warpSum(t);
        if (tid == 0) red[0] = t;
    }
    __syncthreads();
    const float inv = 1.0f / red[0];

    #pragma unroll
    for (int i = 0; i < 8; i++) v[i] *= inv;

    *reinterpret_cast<float4*>(row + base)     = make_float4(v[0], v[1], v[2], v[3]);
    *reinterpret_cast<float4*>(row + base + 4) = make_float4(v[4], v[5], v[6], v[7]);
    __half2 h0 = __floats2half2_rn(v[0], v[1]);
    __half2 h1 = __floats2half2_rn(v[2], v[3]);
    __half2 h2 = __floats2half2_rn(v[4], v[5]);
    __half2 h3 = __floats2half2_rn(v[6], v[7]);
    uint4 hv = make_uint4(*(uint32_t*)&h0, *(uint32_t*)&h1,
                          *(uint32_t*)&h2, *(uint32_t*)&h3);
    *reinterpret_cast<uint4*>(hrow + base) = hv;
}

// ---------------------------------------------------------------------------
// Host-side tensormap construction (driver entry point via cudart; no -lcuda)
// ---------------------------------------------------------------------------
typedef CUresult (*PFN_tmapEncode)(
    CUtensorMap*, CUtensorMapDataType, cuuint32_t, void*,
    const cuuint64_t*, const cuuint64_t*, const cuuint32_t*, const cuuint32_t*,
    CUtensorMapInterleave, CUtensorMapSwizzle, CUtensorMapL2promotion,
    CUtensorMapFloatOOBfill);

static PFN_tmapEncode get_tmap_encode() {
    void* fn = nullptr;
    cudaDriverEntryPointQueryResult st;
#if CUDART_VERSION >= 12050
    cudaGetDriverEntryPointByVersion("cuTensorMapEncodeTiled", &fn, 12000,
                                     cudaEnableDefault, &st);
#else
    cudaGetDriverEntryPoint("cuTensorMapEncodeTiled", &fn, cudaEnableDefault, &st);
#endif
    return (PFN_tmapEncode)fn;
}

static void make_tmap(PFN_tmapEncode enc, CUtensorMap* out, void* base,
                      long long K, long long rows, long long batch,
                      long long rowPitchBytes, long long batchStrideBytes,
                      uint32_t boxK, uint32_t boxRows)
{
    cuuint64_t dims[3]    = { (cuuint64_t)K, (cuuint64_t)rows, (cuuint64_t)batch };
    cuuint64_t strides[2] = { (cuuint64_t)rowPitchBytes, (cuuint64_t)batchStrideBytes };
    cuuint32_t box[3]     = { boxK, boxRows, 1 };
    cuuint32_t es[3]      = { 1, 1, 1 };
    enc(out, CU_TENSOR_MAP_DATA_TYPE_UINT16, 3, base, dims, strides, box, es,
        CU_TENSOR_MAP_INTERLEAVE_NONE, CU_TENSOR_MAP_SWIZZLE_128B,
        CU_TENSOR_MAP_L2_PROMOTION_L2_128B, CU_TENSOR_MAP_FLOAT_OOB_FILL_NONE);
}

// ---------------------------------------------------------------------------
// kernel_launch
// d_in: 0=input [B,S,D], 1=context [B,S,D], 2=Wq, 3=Wk, 4=Wv, 5=Wo ([D,D])
// d_out: output [B,S,D] then weights [B,S,S], fp32.
// ---------------------------------------------------------------------------
extern "C" void kernel_launch(void* const* d_in, const int* in_sizes, int n_in,
                              void* d_out, int out_size)
{
    const float* input   = (const float*)d_in[0];
    const float* context = (const float*)d_in[1];
    const float* Wq      = (const float*)d_in[2];
    const float* Wk      = (const float*)d_in[3];
    const float* Wv      = (const float*)d_in[4];
    const float* Wo      = (const float*)d_in[5];

    float* out     = (float*)d_out;                          // [B,S,D]
    float* weights = out + (long long)BB * SS * DD;          // [B,S,S]

    __half *xh, *ch, *wth, *qh, *kh, *vth, *wh, *ctxh;
    cudaGetSymbolAddress((void**)&xh,   g_XH);
    cudaGetSymbolAddress((void**)&ch,   g_CH);
    cudaGetSymbolAddress((void**)&wth,  g_WTH);
    cudaGetSymbolAddress((void**)&qh,   g_QH);
    cudaGetSymbolAddress((void**)&kh,   g_KH);
    cudaGetSymbolAddress((void**)&vth,  g_VTH);
    cudaGetSymbolAddress((void**)&wh,   g_WH);
    cudaGetSymbolAddress((void**)&ctxh, g_CTXH);
    __half* WqT = wth;
    __half* WkT = wth + 1 * DD * DD;
    __half* WvT = wth + 2 * DD * DD;
    __half* WoT = wth + 3 * DD * DD;

    cudaFuncSetAttribute(gemm_nt_f16,
                         cudaFuncAttributeMaxDynamicSharedMemorySize, SM_TOTAL);

    const dim3 blk(256);
    const dim3 tblk(32, 8);
    const long long SD  = (long long)SS * DD;
    const long long SSq = (long long)SS * SS;
    const long long NX  = (long long)BB * SS * DD;

    // Tensormaps (A and B boxes are 64 x 256)
    PFN_tmapEncode enc = get_tmap_encode();
    CUtensorMap tA_x, tA_c, tB_wq, tB_wk, tB_wv, tB_wo;
    CUtensorMap tA_q, tB_k, tA_w, tB_vt, tA_ctx;
    make_tmap(enc, &tA_x,   xh,  DD, (long long)BB * SS, 1, DD * 2, NX * 2, BK, BM);
    make_tmap(enc, &tA_c,   ch,  DD, (long long)BB * SS, 1, DD * 2, NX * 2, BK, BM);
    make_tmap(enc, &tB_wq,  WqT, DD, DD, 1, DD * 2, (long long)DD * DD * 2, BK, BN);
    make_tmap(enc, &tB_wk,  WkT, DD, DD, 1, DD * 2, (long long)DD * DD * 2, BK, BN);
    make_tmap(enc, &tB_wv,  WvT, DD, DD, 1, DD * 2, (long long)DD * DD * 2, BK, BN);
    make_tmap(enc, &tB_wo,  WoT, DD, DD, 1, DD * 2, (long long)DD * DD * 2, BK, BN);
    make_tmap(enc, &tA_q,   qh,  DD, SS, BB, DD * 2, SD * 2, BK, BM);
    make_tmap(enc, &tB_k,   kh,  DD, SS, BB, DD * 2, SD * 2, BK, BN);
    make_tmap(enc, &tA_w,   wh,  SS, SS, BB, SS * 2, SSq * 2, BK, BM);
    make_tmap(enc, &tB_vt,  vth, SS, DD, BB, SS * 2, SD * 2, BK, BN);
    make_tmap(enc, &tA_ctx, ctxh, DD, (long long)BB * SS, 1, DD * 2, NX * 2, BK, BM);

    // 0) Fused prologue: dual cvt (1 launch) + batched weight transpose (1 launch)
    cvt2_f32_f16<<<(unsigned)((NX / 4 + 255) / 256), blk>>>(input, xh, context, ch, NX);
    {
        dim3 g(DD / 32, DD / 32, 4);
        transpose4_f32_to_f16<<<g, tblk>>>(Wq, Wk, Wv, Wo, wth);
    }

    // Grid: x = N tiles, y = M tiles (BM=256), z = batch
    // 1) Projections: Q,K fp16; V written TRANSPOSED directly (mode 2)
    {
        dim3 g(DD / BN, (BB * SS) / BM, 1);
        gemm_nt_f16<<<g, blk, SM_TOTAL>>>(tA_x, tB_wq, xh, WqT, qh,  DD, DD, 0, 0, 0, 1.0f, 1);
        gemm_nt_f16<<<g, blk, SM_TOTAL>>>(tA_c, tB_wk, ch, WkT, kh,  DD, DD, 0, 0, 0, 1.0f, 1);
        gemm_nt_f16<<<g, blk, SM_TOTAL>>>(tA_c, tB_wv, ch, WvT, vth, DD, DD, 0, 0, 0, 1.0f, 2);
    }

    // 2) scores = Q @ K^T * (1/sqrt(D)) -> weights slice (fp32 out)
    {
        dim3 g(SS / BN, SS / BM, BB);
        gemm_nt_f16<<<g, blk, SM_TOTAL>>>(tA_q, tB_k, qh, kh, weights, DD, SS, SD, SD, SSq, 0.03125f, 0);
    }

    // 3) softmax in place (fp32) + fp16 copy
    softmax_rows<<<BB * SS, blk>>>(weights, wh);

    // 4) ctx = weights @ V == NT with V^T rows (fp16 out)
    {
        dim3 g(DD / BN, SS / BM, BB);
        gemm_nt_f16<<<g, blk, SM_TOTAL>>>(tA_w, tB_vt, wh, vth, ctxh, SS, DD, SSq, SD, SD, 1.0f, 1);
    }

    // 5) output = ctx @ Wo == NT with Wo^T (fp32 out)
    {
        dim3 g(DD / BN, (BB * SS) / BM, 1);
        gemm_nt_f16<<<g, blk, SM_TOTAL>>>(tA_ctx, tB_wo, ctxh, WoT, out, DD, DD, 0, 0, 0, 1.0f, 0);
    }
}